// round 12
// baseline (speedup 1.0000x reference)
#include <cuda_runtime.h>
#include <cuda_bf16.h>
#include <stdint.h>
#include <math.h>

#define Bv    32
#define NCLS  20
#define Tt    2048
#define Dd    2048
#define Ll    128

// FSD scale: 10*log2(e)  (gamma=0.1 -> log2 x10 domain); back: ln(2)/10
#define FSD_SCALE 14.426950408889634f
#define FSD_UNSCALE 0.06931471805599453f

// ---------------------------------------------------------------------------
// Device scratch (only tiny result buffers now)
// ---------------------------------------------------------------------------
__device__ float g_small[32][4];            // per-batch {cls, guide, feat, sparse}
__device__ float g_dpres[64];               // 0..31 fsd, 32..63 lcs
__device__ unsigned int g_done = 0;

// ---------------------------------------------------------------------------
// helpers
// ---------------------------------------------------------------------------
__device__ __forceinline__ uint32_t swz(uint32_t row, uint32_t col) {
    return row * 64u + ((((col >> 3) ^ ((row >> 1) & 3u)) << 4)) + ((col & 7u) << 1);
}
__device__ __forceinline__ uint32_t pk_bf2(float lo, float hi) {
    __nv_bfloat162 h = __floats2bfloat162_rn(lo, hi);
    return *(uint32_t*)&h;
}
__device__ __forceinline__ void ldsm4(uint32_t addr, uint32_t& r0, uint32_t& r1,
                                      uint32_t& r2, uint32_t& r3) {
    asm volatile("ldmatrix.sync.aligned.m8n8.x4.shared.b16 {%0,%1,%2,%3}, [%4];"
                 : "=r"(r0), "=r"(r1), "=r"(r2), "=r"(r3) : "r"(addr));
}
__device__ __forceinline__ void mma16816(float* c, const uint32_t* a,
                                         uint32_t b0, uint32_t b1) {
    asm volatile("mma.sync.aligned.m16n8k16.row.col.f32.bf16.bf16.f32 "
                 "{%0,%1,%2,%3}, {%4,%5,%6,%7}, {%8,%9}, {%0,%1,%2,%3};"
                 : "+f"(c[0]), "+f"(c[1]), "+f"(c[2]), "+f"(c[3])
                 : "r"(a[0]), "r"(a[1]), "r"(a[2]), "r"(a[3]), "r"(b0), "r"(b1));
}
__device__ __forceinline__ float ex2f(float x) {
    float y; asm("ex2.approx.f32 %0, %1;" : "=f"(y) : "f"(x)); return y;
}
__device__ __forceinline__ float lg2f(float x) {
    float y; asm("lg2.approx.f32 %0, %1;" : "=f"(y) : "f"(x)); return y;
}

// smem layout: [0, 32768) two 16KB gemm stages (A 8K + B 8K each);
//              [32768, 32768+131072) DP matrix (float2 for FSD, float for LCS)
#define STG     16384
#define OUT_OFF 32768
#define SMEM_TOTAL (OUT_OFF + 131072)

#define DPK 16      // diagonals per epoch
#define NSUP 19     // supersteps: warp w active tau in [3w, 3w+10)

// ---------------------------------------------------------------------------
// ONE kernel, 96 blocks:
//  [0,32)  FSD pair blocks: 2x (128x128xK=1024) GEMM -> smem float2, then DP
//  [32,64) LCS pair blocks: 1x (128x128xK=2048) GEMM -> smem float, then DP
//  [64,96) small-loss blocks
// Last finishing block combines into out[0].
// ---------------------------------------------------------------------------
__global__ __launch_bounds__(256, 1)
void k_all(const float* __restrict__ lcs,
           const float* __restrict__ act,
           const float* __restrict__ bak,
           const int* __restrict__ pos,
           const int* __restrict__ neg,
           const float* __restrict__ xi,
           const float* __restrict__ xc,
           const float* __restrict__ xb,
           const float* __restrict__ vid,
           const float* __restrict__ att,
           const float* __restrict__ fi,
           const float* __restrict__ fc,
           const float* __restrict__ fb,
           const float* __restrict__ cas,
           float* __restrict__ outp) {
    extern __shared__ char sm[];
    __shared__ float rnA[128], rnB[128];
    __shared__ float bnd[5][256];
    __shared__ float red[256];

    int blk = blockIdx.x;
    int tid = threadIdx.x;

    // ---------------- small-loss blocks ----------------
    if (blk >= 64) {
        int bb = blk - 64;
        float guide = 0.0f, sparse = 0.0f, si2 = 0.0f, sc2 = 0.0f, sb2 = 0.0f;
        for (int tt = tid; tt < Tt; tt += 256) {
            float cas20 = cas[((size_t)bb * Tt + tt) * (NCLS + 1) + NCLS];
            float a0 = att[((size_t)bb * Tt + tt) * 3 + 0];
            float a1 = att[((size_t)bb * Tt + tt) * 3 + 1];
            guide  += fabsf(1.0f - cas20 - a0);
            sparse += a0 + a1;
        }
        for (int k = tid; k < Dd; k += 256) {
            float v1 = fi[(size_t)bb * Dd + k];
            float v2 = fc[(size_t)bb * Dd + k];
            float v3 = fb[(size_t)bb * Dd + k];
            si2 += v1 * v1; sc2 += v2 * v2; sb2 += v3 * v3;
        }
        float vals[5] = {guide, sparse, si2, sc2, sb2};
#pragma unroll
        for (int v = 0; v < 5; ++v) {
            red[tid] = vals[v];
            __syncthreads();
            for (int s = 128; s > 0; s >>= 1) {
                if (tid < s) red[tid] += red[tid + s];
                __syncthreads();
            }
            vals[v] = red[0];
            __syncthreads();
        }
        if (tid == 0) {
            float ni = sqrtf(vals[2]);
            float nc = sqrtf(vals[3]);
            float nb = sqrtf(vals[4]);
            float f1 = fmaxf(50.0f - ni + nc, 0.0f);
            float f2 = fmaxf(50.0f - nc + nb, 0.0f);
            float feat = (f1 + f2 + nb) * (f1 + f2 + nb);
            float sv = 0.0f, s_i = 0.0f, s_c = 0.0f;
            for (int c = 0; c < NCLS; ++c) {
                float l = vid[bb * NCLS + c];
                sv  += l;
                s_i += l * logf(xi[bb * (NCLS + 1) + c] + 1e-45f);
                s_c += l * logf(xc[bb * (NCLS + 1) + c] + 1e-45f);
            }
            float inst_b = -s_i / sv;
            float cont_b = -(s_c + logf(xc[bb * (NCLS + 1) + NCLS] + 1e-45f)) / (sv + 1.0f);
            float back_b = -logf(xb[bb * (NCLS + 1) + NCLS] + 1e-45f);
            g_small[bb][0] = inst_b + cont_b + back_b;
            g_small[bb][1] = vals[0];
            g_small[bb][2] = feat;
            g_small[bb][3] = vals[1];
            __threadfence();
            unsigned vd = atomicAdd(&g_done, 1u);
            if (vd == 95u) {
                // everyone else already finished; combine
                float cls = 0.f, guideS = 0.f, featS = 0.f, sparseS = 0.f;
                for (int i = 0; i < 32; ++i) {
                    cls += g_small[i][0]; guideS += g_small[i][1];
                    featS += g_small[i][2]; sparseS += g_small[i][3];
                }
                volatile float* dp = g_dpres;
                float aa = 0.f, ab = 0.f, pl = 0.f, nl = 0.f;
                for (int i = 0; i < 16; ++i) {
                    aa += dp[i]; ab += dp[16 + i];
                    pl += dp[32 + i]; nl += dp[48 + i];
                }
                float acm = cls / 32.0f + guideS / 32.0f
                          + 5e-5f * (featS / 32.0f) + 2e-4f * (sparseS / 64.0f);
                outp[0] = acm + 0.1f * ((nl - pl) / 16.0f)
                              + 0.1f * ((ab - aa) / 16.0f);
                g_done = 0;
            }
        }
        return;
    }

    // ---------------- pair blocks: GEMM into smem ----------------
    bool isFsd = (blk < 32);
    int p = isFsd ? blk : blk - 32;
    int i0 = (p < 16) ? pos[2 * p]     : neg[2 * (p - 16)];
    int i1 = (p < 16) ? pos[2 * p + 1] : neg[2 * (p - 16) + 1];
    const float* Abase;
    const float* Bbase;
    if (isFsd) {
        Abase = act + (size_t)i0 * Ll * Dd;
        Bbase = ((p < 16) ? act : bak) + (size_t)i1 * Ll * Dd;
    } else {
        Abase = lcs + (size_t)i0 * Ll * Dd;
        Bbase = lcs + (size_t)i1 * Ll * Dd;
    }

    uint32_t smemBase = (uint32_t)__cvta_generic_to_shared(sm);
    int lane = tid & 31;
    int warp = tid >> 5;
    int wm = warp >> 1;            // 0..3
    int wn = warp & 1;             // 0..1

    int aRow0 = tid >> 2;          // 0..63
    int aRow1 = 64 + (tid >> 2);   // 64..127
    int kg    = tid & 3;

    int grp = lane >> 3, r8 = lane & 7;
    uint32_t aRowL = (uint32_t)(r8 + (grp & 1) * 8);
    uint32_t aColL = (uint32_t)((grp >> 1) * 8);
    uint32_t bRowL = (uint32_t)(r8 + (grp >> 1) * 8);
    uint32_t bColL = (uint32_t)((grp & 1) * 8);

    int npass  = isFsd ? 2 : 1;
    int ksteps = isFsd ? 32 : 64;

    for (int pass = 0; pass < npass; ++pass) {
        int koff = pass << 10;     // FSD halves; LCS pass 0
        const float* pA0 = Abase + (size_t)aRow0 * Dd + koff + kg * 8;
        const float* pA1 = Abase + (size_t)aRow1 * Dd + koff + kg * 8;
        const float* pB0 = Bbase + (size_t)aRow0 * Dd + koff + kg * 8;
        const float* pB1 = Bbase + (size_t)aRow1 * Dd + koff + kg * 8;

        float acc[2][8][4];
#pragma unroll
        for (int i = 0; i < 2; ++i)
#pragma unroll
            for (int j = 0; j < 8; ++j)
#pragma unroll
                for (int q = 0; q < 4; ++q) acc[i][j][q] = 0.0f;

        float sqA0 = 0.f, sqA1 = 0.f, sqB0 = 0.f, sqB1 = 0.f;
        float4 bA0[2], bA1[2], bB0[2], bB1[2];

        bA0[0] = *(const float4*)(pA0);     bA0[1] = *(const float4*)(pA0 + 4);
        bA1[0] = *(const float4*)(pA1);     bA1[1] = *(const float4*)(pA1 + 4);
        bB0[0] = *(const float4*)(pB0);     bB0[1] = *(const float4*)(pB0 + 4);
        bB1[0] = *(const float4*)(pB1);     bB1[1] = *(const float4*)(pB1 + 4);

        // stage fill helper (sq accumulate + bf16 pack + swizzled store)
        auto fill = [&](char* st) {
            const float* f0 = (const float*)&bA0[0];
            const float* f1 = (const float*)&bA1[0];
            const float* f2 = (const float*)&bB0[0];
            const float* f3 = (const float*)&bB1[0];
#pragma unroll
            for (int q = 0; q < 8; ++q) {
                sqA0 = fmaf(f0[q], f0[q], sqA0);
                sqA1 = fmaf(f1[q], f1[q], sqA1);
                sqB0 = fmaf(f2[q], f2[q], sqB0);
                sqB1 = fmaf(f3[q], f3[q], sqB1);
            }
            uint4 v;
            v.x = pk_bf2(f0[0], f0[1]); v.y = pk_bf2(f0[2], f0[3]);
            v.z = pk_bf2(f0[4], f0[5]); v.w = pk_bf2(f0[6], f0[7]);
            *(uint4*)(st + swz((uint32_t)aRow0, (uint32_t)(kg * 8))) = v;
            v.x = pk_bf2(f1[0], f1[1]); v.y = pk_bf2(f1[2], f1[3]);
            v.z = pk_bf2(f1[4], f1[5]); v.w = pk_bf2(f1[6], f1[7]);
            *(uint4*)(st + swz((uint32_t)aRow1, (uint32_t)(kg * 8))) = v;
            v.x = pk_bf2(f2[0], f2[1]); v.y = pk_bf2(f2[2], f2[3]);
            v.z = pk_bf2(f2[4], f2[5]); v.w = pk_bf2(f2[6], f2[7]);
            *(uint4*)(st + 8192 + swz((uint32_t)aRow0, (uint32_t)(kg * 8))) = v;
            v.x = pk_bf2(f3[0], f3[1]); v.y = pk_bf2(f3[2], f3[3]);
            v.z = pk_bf2(f3[4], f3[5]); v.w = pk_bf2(f3[6], f3[7]);
            *(uint4*)(st + 8192 + swz((uint32_t)aRow1, (uint32_t)(kg * 8))) = v;
        };

        fill(sm);
        __syncthreads();

        for (int kt = 0; kt < ksteps; ++kt) {
            if (kt + 1 < ksteps) {
                int k0 = (kt + 1) * 32;
                bA0[0] = *(const float4*)(pA0 + k0); bA0[1] = *(const float4*)(pA0 + k0 + 4);
                bA1[0] = *(const float4*)(pA1 + k0); bA1[1] = *(const float4*)(pA1 + k0 + 4);
                bB0[0] = *(const float4*)(pB0 + k0); bB0[1] = *(const float4*)(pB0 + k0 + 4);
                bB1[0] = *(const float4*)(pB1 + k0); bB1[1] = *(const float4*)(pB1 + k0 + 4);
            }

            uint32_t stBase = smemBase + (uint32_t)(kt & 1) * STG;
#pragma unroll
            for (int ks = 0; ks < 2; ++ks) {
                int k0 = ks * 16;
                uint32_t afr[2][4];
#pragma unroll
                for (int tm = 0; tm < 2; ++tm) {
                    uint32_t m0 = (uint32_t)(wm * 32 + tm * 16);
                    uint32_t addrA = stBase + swz(m0 + aRowL, (uint32_t)k0 + aColL);
                    ldsm4(addrA, afr[tm][0], afr[tm][1], afr[tm][2], afr[tm][3]);
                }
                uint32_t bfr[4][4];
#pragma unroll
                for (int tb = 0; tb < 4; ++tb) {
                    uint32_t n0 = (uint32_t)(wn * 64 + tb * 16);
                    uint32_t addrB = stBase + 8192u + swz(n0 + bRowL, (uint32_t)k0 + bColL);
                    ldsm4(addrB, bfr[tb][0], bfr[tb][1], bfr[tb][2], bfr[tb][3]);
                }
#pragma unroll
                for (int tm = 0; tm < 2; ++tm)
#pragma unroll
                    for (int tn = 0; tn < 8; ++tn) {
                        int tb = tn >> 1, wh = tn & 1;
                        mma16816(acc[tm][tn], afr[tm], bfr[tb][wh * 2], bfr[tb][wh * 2 + 1]);
                    }
            }

            if (kt + 1 < ksteps)
                fill(sm + ((kt + 1) & 1) * STG);
            __syncthreads();
        }

        // norms
        sqA0 += __shfl_xor_sync(0xffffffffu, sqA0, 1);
        sqA0 += __shfl_xor_sync(0xffffffffu, sqA0, 2);
        sqA1 += __shfl_xor_sync(0xffffffffu, sqA1, 1);
        sqA1 += __shfl_xor_sync(0xffffffffu, sqA1, 2);
        sqB0 += __shfl_xor_sync(0xffffffffu, sqB0, 1);
        sqB0 += __shfl_xor_sync(0xffffffffu, sqB0, 2);
        sqB1 += __shfl_xor_sync(0xffffffffu, sqB1, 1);
        sqB1 += __shfl_xor_sync(0xffffffffu, sqB1, 2);
        if ((tid & 3) == 0) {
            rnA[aRow0] = rsqrtf(sqA0);
            rnA[aRow1] = rsqrtf(sqA1);
            rnB[aRow0] = rsqrtf(sqB0);
            rnB[aRow1] = rsqrtf(sqB1);
        }
        __syncthreads();

        // epilogue into DP smem
        int g8 = lane >> 2, tq = lane & 3;
        float2* o2 = (float2*)(sm + OUT_OFF);
        float*  of = (float*)(sm + OUT_OFF);
#pragma unroll
        for (int tm = 0; tm < 2; ++tm) {
            int row0 = wm * 32 + tm * 16 + g8;
            int row1 = row0 + 8;
            float ra0 = rnA[row0], ra1 = rnA[row1];
#pragma unroll
            for (int tn = 0; tn < 8; ++tn) {
                int col = wn * 64 + tn * 8 + 2 * tq;
                float rb0 = rnB[col], rb1 = rnB[col + 1];
                float v00 = acc[tm][tn][0] * ra0 * rb0;
                float v01 = acc[tm][tn][1] * ra0 * rb1;
                float v10 = acc[tm][tn][2] * ra1 * rb0;
                float v11 = acc[tm][tn][3] * ra1 * rb1;
                if (isFsd) {
                    v00 *= FSD_SCALE; v01 *= FSD_SCALE;
                    v10 *= FSD_SCALE; v11 *= FSD_SCALE;
                    if (pass == 0) {
                        o2[row0 * 128 + col].x = v00; o2[row0 * 128 + col + 1].x = v01;
                        o2[row1 * 128 + col].x = v10; o2[row1 * 128 + col + 1].x = v11;
                    } else {
                        o2[row0 * 128 + col].y = v00; o2[row0 * 128 + col + 1].y = v01;
                        o2[row1 * 128 + col].y = v10; o2[row1 * 128 + col + 1].y = v11;
                    }
                } else {
                    v00 = fmaxf(0.0f, v00 - 0.8f) * 5.0f;
                    v01 = fmaxf(0.0f, v01 - 0.8f) * 5.0f;
                    v10 = fmaxf(0.0f, v10 - 0.8f) * 5.0f;
                    v11 = fmaxf(0.0f, v11 - 0.8f) * 5.0f;
                    *(float2*)(of + row0 * 128 + col) = make_float2(v00, v01);
                    *(float2*)(of + row1 * 128 + col) = make_float2(v10, v11);
                }
            }
        }
        __syncthreads();
    }

    // ---------------- DP (4 warps active, lagged-epoch, branchless) --------
    if (tid < 128) {
        bnd[4][tid] = 0.0f;
        bnd[4][tid + 128] = 0.0f;
    }
    __syncthreads();

    int w = tid >> 5, lane2 = tid & 31;
    int r = tid & 127;
    int wb = (w == 0) ? 4 : ((w < 4) ? (w - 1) : 4);
    const float* bndp = bnd[wb];
    bool dpwarp = (w < 4);
    float v = 0.0f, d = 0.0f;

    if (isFsd) {
        const float2* mrow = ((const float2*)(sm + OUT_OFF)) + r * 127;
        for (int tau = 0; tau < NSUP; ++tau) {
            if (dpwarp && tau >= 3 * w && tau < 3 * w + 10) {
                int s0 = (tau - w) * DPK;
#pragma unroll
                for (int k = 0; k < DPK; ++k) {
                    int s = s0 + k;
                    int sl = (s < 255) ? s : 254;
                    int sm1 = s - 1; if (sm1 < 0) sm1 = 0;
                    float bv = bndp[sm1];
                    float au = __shfl_up_sync(0xffffffffu, v, 1);
                    float a = (lane2 == 0) ? bv : au;
                    float2 mg = mrow[sl];
                    float x1 = mg.y + a, x2 = mg.y + v;
                    float mx = fmaxf(fmaxf(d, x1), x2);
                    float e = ex2f(d - mx) + ex2f(x1 - mx) + ex2f(x2 - mx);
                    float nv = mg.x + mx + lg2f(e);
                    v = ((unsigned)(s - r) < 128u) ? nv : v;
                    d = a;
                    if (lane2 == 31) bnd[w][s] = v;
                }
            }
            __syncthreads();
        }
        if (tid == 127) g_dpres[blk] = v * FSD_UNSCALE;
    } else {
        const float* mrow = ((const float*)(sm + OUT_OFF)) + r * 127;
        for (int tau = 0; tau < NSUP; ++tau) {
            if (dpwarp && tau >= 3 * w && tau < 3 * w + 10) {
                int s0 = (tau - w) * DPK;
#pragma unroll
                for (int k = 0; k < DPK; ++k) {
                    int s = s0 + k;
                    int sl = (s < 255) ? s : 254;
                    int sm1 = s - 1; if (sm1 < 0) sm1 = 0;
                    float bv = bndp[sm1];
                    float au = __shfl_up_sync(0xffffffffu, v, 1);
                    float a = (lane2 == 0) ? bv : au;
                    float sv = mrow[sl];
                    float nv = (sv > 0.5f) ? d + sv : fmaxf(a, v);
                    v = ((unsigned)(s - r) < 128u) ? nv : v;
                    d = a;
                    if (lane2 == 31) bnd[w][s] = v;
                }
            }
            __syncthreads();
        }
        if (tid == 127) g_dpres[blk] = v;
    }

    // completion + final combine by the last finishing block
    if (tid == 127) {
        __threadfence();
        unsigned vdone = atomicAdd(&g_done, 1u);
        if (vdone == 95u) {
            float cls = 0.f, guide = 0.f, feat = 0.f, sparse = 0.f;
#pragma unroll 4
            for (int i = 0; i < 32; ++i) {
                cls    += g_small[i][0];
                guide  += g_small[i][1];
                feat   += g_small[i][2];
                sparse += g_small[i][3];
            }
            volatile float* dp = g_dpres;
            float aa = 0.f, ab = 0.f, pl = 0.f, nl = 0.f;
#pragma unroll 4
            for (int i = 0; i < 16; ++i) {
                aa += dp[i];
                ab += dp[16 + i];
                pl += dp[32 + i];
                nl += dp[48 + i];
            }
            float acm = cls / 32.0f + guide / 32.0f
                      + 5e-5f * (feat / 32.0f) + 2e-4f * (sparse / 64.0f);
            outp[0] = acm + 0.1f * ((nl - pl) / 16.0f)
                          + 0.1f * ((ab - aa) / 16.0f);
            g_done = 0;
        }
    }
}

// ---------------------------------------------------------------------------
// Launch
// ---------------------------------------------------------------------------
extern "C" void kernel_launch(void* const* d_in, const int* in_sizes, int n_in,
                              void* d_out, int out_size) {
    const float* xi  = (const float*)d_in[0];
    const float* xc  = (const float*)d_in[1];
    const float* xb  = (const float*)d_in[2];
    const float* vid = (const float*)d_in[3];
    const float* att = (const float*)d_in[4];
    const float* fi  = (const float*)d_in[5];
    const float* fc  = (const float*)d_in[6];
    const float* fb  = (const float*)d_in[7];
    const float* cas = (const float*)d_in[8];
    const float* lcs = (const float*)d_in[9];
    const float* act = (const float*)d_in[10];
    const float* bak = (const float*)d_in[11];
    const int*   pos = (const int*)d_in[12];
    const int*   neg = (const int*)d_in[13];
    float* out = (float*)d_out;

    cudaFuncSetAttribute(k_all, cudaFuncAttributeMaxDynamicSharedMemorySize, SMEM_TOTAL);

    k_all<<<96, 256, SMEM_TOTAL>>>(lcs, act, bak, pos, neg,
                                   xi, xc, xb, vid, att, fi, fc, fb, cas, out);
}

// round 15
// speedup vs baseline: 1.4576x; 1.4576x over previous
#include <cuda_runtime.h>
#include <cuda_bf16.h>
#include <stdint.h>
#include <math.h>

#define Bv    32
#define NCLS  20
#define Tt    2048
#define Dd    2048
#define Ll    128

// FSD scale: 10*log2(e)  (gamma=0.1 -> log2 x10 domain); back: ln(2)/10
#define FSD_SCALE 14.426950408889634f
#define FSD_UNSCALE 0.06931471805599453f

// ---------------------------------------------------------------------------
// Device scratch
// ---------------------------------------------------------------------------
__device__ float g_sim_m[32 * Ll * Ll];     // FSD m (x FSD_SCALE)
__device__ float g_sim_g[32 * Ll * Ll];     // FSD g (x FSD_SCALE)
__device__ float g_dotL0[32 * Ll * Ll];     // LCS raw dots, K half 0
__device__ float g_dotL1[32 * Ll * Ll];     // LCS raw dots, K half 1
__device__ float g_nAL[2][32][128];         // LCS A sq partials
__device__ float g_nBL[2][32][128];         // LCS B sq partials
__device__ float g_small[32][4];            // per-batch {cls, guide, feat, sparse}
__device__ float g_dpres[64];               // 0..31 fsd, 32..63 lcs
__device__ unsigned int g_done = 0;

// ---------------------------------------------------------------------------
// GEMM helpers
// ---------------------------------------------------------------------------
__device__ __forceinline__ uint32_t swz(uint32_t row, uint32_t col) {
    return row * 64u + ((((col >> 3) ^ ((row >> 1) & 3u)) << 4)) + ((col & 7u) << 1);
}
__device__ __forceinline__ uint32_t pk_bf2(float lo, float hi) {
    __nv_bfloat162 h = __floats2bfloat162_rn(lo, hi);
    return *(uint32_t*)&h;
}
__device__ __forceinline__ void ldsm4(uint32_t addr, uint32_t& r0, uint32_t& r1,
                                      uint32_t& r2, uint32_t& r3) {
    asm volatile("ldmatrix.sync.aligned.m8n8.x4.shared.b16 {%0,%1,%2,%3}, [%4];"
                 : "=r"(r0), "=r"(r1), "=r"(r2), "=r"(r3) : "r"(addr));
}
__device__ __forceinline__ void mma16816(float* c, const uint32_t* a,
                                         uint32_t b0, uint32_t b1) {
    asm volatile("mma.sync.aligned.m16n8k16.row.col.f32.bf16.bf16.f32 "
                 "{%0,%1,%2,%3}, {%4,%5,%6,%7}, {%8,%9}, {%0,%1,%2,%3};"
                 : "+f"(c[0]), "+f"(c[1]), "+f"(c[2]), "+f"(c[3])
                 : "r"(a[0]), "r"(a[1]), "r"(a[2]), "r"(a[3]), "r"(b0), "r"(b1));
}

#define STAGE_BYTES 12288
#define KSTEPS 32

// ---------------------------------------------------------------------------
// k_gemm: 288 blocks.
//  [0,128) FSD final. [128,256) LCS split-K raw. [256,288) small-loss blocks.
// ---------------------------------------------------------------------------
__global__ __launch_bounds__(256, 2)
void k_gemm(const float* __restrict__ lcs,
            const float* __restrict__ act,
            const float* __restrict__ bak,
            const int* __restrict__ pos,
            const int* __restrict__ neg,
            const float* __restrict__ xi,
            const float* __restrict__ xc,
            const float* __restrict__ xb,
            const float* __restrict__ vid,
            const float* __restrict__ att,
            const float* __restrict__ fi,
            const float* __restrict__ fc,
            const float* __restrict__ fb,
            const float* __restrict__ cas) {
    int blk = blockIdx.x;
    int tid = threadIdx.x;

    __shared__ uint4 smBuf[2 * STAGE_BYTES / 16];
    __shared__ float rnAs[128];
    __shared__ float rnBs[64];

    if (blk >= 256) {
        __shared__ float red[256];
        int bb = blk - 256;
        float guide = 0.0f, sparse = 0.0f, si2 = 0.0f, sc2 = 0.0f, sb2 = 0.0f;
        for (int tt = tid; tt < Tt; tt += 256) {
            float cas20 = cas[((size_t)bb * Tt + tt) * (NCLS + 1) + NCLS];
            float a0 = att[((size_t)bb * Tt + tt) * 3 + 0];
            float a1 = att[((size_t)bb * Tt + tt) * 3 + 1];
            guide  += fabsf(1.0f - cas20 - a0);
            sparse += a0 + a1;
        }
        for (int k = tid; k < Dd; k += 256) {
            float v1 = fi[(size_t)bb * Dd + k];
            float v2 = fc[(size_t)bb * Dd + k];
            float v3 = fb[(size_t)bb * Dd + k];
            si2 += v1 * v1; sc2 += v2 * v2; sb2 += v3 * v3;
        }
        float vals[5] = {guide, sparse, si2, sc2, sb2};
#pragma unroll
        for (int v = 0; v < 5; ++v) {
            red[tid] = vals[v];
            __syncthreads();
            for (int s = 128; s > 0; s >>= 1) {
                if (tid < s) red[tid] += red[tid + s];
                __syncthreads();
            }
            vals[v] = red[0];
            __syncthreads();
        }
        if (tid == 0) {
            float ni = sqrtf(vals[2]);
            float nc = sqrtf(vals[3]);
            float nb = sqrtf(vals[4]);
            float f1 = fmaxf(50.0f - ni + nc, 0.0f);
            float f2 = fmaxf(50.0f - nc + nb, 0.0f);
            float feat = (f1 + f2 + nb) * (f1 + f2 + nb);
            float sv = 0.0f, s_i = 0.0f, s_c = 0.0f;
            for (int c = 0; c < NCLS; ++c) {
                float l = vid[bb * NCLS + c];
                sv  += l;
                s_i += l * logf(xi[bb * (NCLS + 1) + c] + 1e-45f);
                s_c += l * logf(xc[bb * (NCLS + 1) + c] + 1e-45f);
            }
            float inst_b = -s_i / sv;
            float cont_b = -(s_c + logf(xc[bb * (NCLS + 1) + NCLS] + 1e-45f)) / (sv + 1.0f);
            float back_b = -logf(xb[bb * (NCLS + 1) + NCLS] + 1e-45f);
            g_small[bb][0] = inst_b + cont_b + back_b;
            g_small[bb][1] = vals[0];
            g_small[bb][2] = feat;
            g_small[bb][3] = vals[1];
        }
        return;
    }

    const float *Abase, *Bbase;
    float* out;
    int mode, colTile, p_idx, kh = 0;

    if (blk < 128) {
        int f = blk >> 1;
        colTile = (blk & 1) * 64;
        int p = f >> 1;
        int half = f & 1;
        p_idx = p;
        int i0 = (p < 16) ? pos[2 * p]     : neg[2 * (p - 16)];
        int i1 = (p < 16) ? pos[2 * p + 1] : neg[2 * (p - 16) + 1];
        Abase = act + (size_t)i0 * Ll * Dd + half * 1024;
        if (p < 16)
            Bbase = act + (size_t)i1 * Ll * Dd + half * 1024;
        else
            Bbase = bak + (size_t)i1 * Ll * Dd + half * 1024;
        out = (half ? g_sim_g : g_sim_m) + (size_t)p * Ll * Ll;
        mode = 0;
    } else {
        int q = blk - 128;
        int p = q >> 2;
        colTile = ((q >> 1) & 1) * 64;
        kh = q & 1;
        p_idx = p;
        int i0 = (p < 16) ? pos[2 * p]     : neg[2 * (p - 16)];
        int i1 = (p < 16) ? pos[2 * p + 1] : neg[2 * (p - 16) + 1];
        Abase = lcs + (size_t)i0 * Ll * Dd + kh * 1024;
        Bbase = lcs + (size_t)i1 * Ll * Dd + kh * 1024;
        out = (kh ? g_dotL1 : g_dotL0) + (size_t)p * Ll * Ll;
        mode = 1;
    }
    Bbase += (size_t)colTile * Dd;

    char* smc = (char*)smBuf;
    uint32_t smemBase = (uint32_t)__cvta_generic_to_shared(smc);

    int lane = tid & 31;
    int warp = tid >> 5;
    int wm = warp >> 1;
    int wn = warp & 1;

    int aRow0 = tid >> 2,            aKg0 = tid & 3;
    int aRow1 = (tid + 256) >> 2,    aKg1 = tid & 3;
    int bRow  = tid >> 2,            bKg  = tid & 3;

    float acc[2][4][4];
#pragma unroll
    for (int i = 0; i < 2; ++i)
#pragma unroll
        for (int j = 0; j < 4; ++j)
#pragma unroll
            for (int q2 = 0; q2 < 4; ++q2) acc[i][j][q2] = 0.0f;

    float sqA0 = 0.0f, sqA1 = 0.0f, sqB = 0.0f;
    float4 bufA[2][2], bufB[2];

    const float* pA0 = Abase + (size_t)aRow0 * Dd + aKg0 * 8;
    const float* pA1 = Abase + (size_t)aRow1 * Dd + aKg1 * 8;
    const float* pB  = Bbase + (size_t)bRow  * Dd + bKg  * 8;

    bufA[0][0] = *(const float4*)(pA0);
    bufA[0][1] = *(const float4*)(pA0 + 4);
    bufA[1][0] = *(const float4*)(pA1);
    bufA[1][1] = *(const float4*)(pA1 + 4);
    bufB[0]    = *(const float4*)(pB);
    bufB[1]    = *(const float4*)(pB + 4);

    {
        const float* fa0 = (const float*)&bufA[0][0];
        const float* fa1 = (const float*)&bufA[1][0];
        const float* fbb = (const float*)&bufB[0];
#pragma unroll
        for (int q2 = 0; q2 < 8; ++q2) {
            sqA0 = fmaf(fa0[q2], fa0[q2], sqA0);
            sqA1 = fmaf(fa1[q2], fa1[q2], sqA1);
            sqB  = fmaf(fbb[q2], fbb[q2], sqB);
        }
        uint4 v;
        v.x = pk_bf2(fa0[0], fa0[1]); v.y = pk_bf2(fa0[2], fa0[3]);
        v.z = pk_bf2(fa0[4], fa0[5]); v.w = pk_bf2(fa0[6], fa0[7]);
        *(uint4*)(smc + swz(aRow0, aKg0 * 8)) = v;
        v.x = pk_bf2(fa1[0], fa1[1]); v.y = pk_bf2(fa1[2], fa1[3]);
        v.z = pk_bf2(fa1[4], fa1[5]); v.w = pk_bf2(fa1[6], fa1[7]);
        *(uint4*)(smc + swz(aRow1, aKg1 * 8)) = v;
        v.x = pk_bf2(fbb[0], fbb[1]); v.y = pk_bf2(fbb[2], fbb[3]);
        v.z = pk_bf2(fbb[4], fbb[5]); v.w = pk_bf2(fbb[6], fbb[7]);
        *(uint4*)(smc + 8192 + swz(bRow, bKg * 8)) = v;
    }
    __syncthreads();

    int grp = lane >> 3, r8 = lane & 7;
    uint32_t aRowL = (uint32_t)(r8 + (grp & 1) * 8);
    uint32_t aColL = (uint32_t)((grp >> 1) * 8);
    uint32_t bRowL = (uint32_t)(r8 + (grp >> 1) * 8);
    uint32_t bColL = (uint32_t)((grp & 1) * 8);

    for (int kt = 0; kt < KSTEPS; ++kt) {
        if (kt + 1 < KSTEPS) {
            int k0 = (kt + 1) * 32;
            bufA[0][0] = *(const float4*)(pA0 + k0);
            bufA[0][1] = *(const float4*)(pA0 + k0 + 4);
            bufA[1][0] = *(const float4*)(pA1 + k0);
            bufA[1][1] = *(const float4*)(pA1 + k0 + 4);
            bufB[0]    = *(const float4*)(pB + k0);
            bufB[1]    = *(const float4*)(pB + k0 + 4);
        }

        uint32_t stBase = smemBase + (uint32_t)(kt & 1) * STAGE_BYTES;
#pragma unroll
        for (int ks = 0; ks < 2; ++ks) {
            int k0 = ks * 16;
            uint32_t afr[2][4];
#pragma unroll
            for (int tm = 0; tm < 2; ++tm) {
                uint32_t m0 = (uint32_t)(wm * 32 + tm * 16);
                uint32_t addrA = stBase + swz(m0 + aRowL, (uint32_t)k0 + aColL);
                ldsm4(addrA, afr[tm][0], afr[tm][1], afr[tm][2], afr[tm][3]);
            }
            uint32_t bfr[2][4];
#pragma unroll
            for (int tb = 0; tb < 2; ++tb) {
                uint32_t n0 = (uint32_t)(wn * 32 + tb * 16);
                uint32_t addrB = stBase + 8192u + swz(n0 + bRowL, (uint32_t)k0 + bColL);
                ldsm4(addrB, bfr[tb][0], bfr[tb][1], bfr[tb][2], bfr[tb][3]);
            }
#pragma unroll
            for (int tm = 0; tm < 2; ++tm)
#pragma unroll
                for (int tn = 0; tn < 4; ++tn) {
                    int tb = tn >> 1, wh = tn & 1;
                    mma16816(acc[tm][tn], afr[tm], bfr[tb][wh * 2], bfr[tb][wh * 2 + 1]);
                }
        }

        if (kt + 1 < KSTEPS) {
            char* nst = smc + ((kt + 1) & 1) * STAGE_BYTES;
            const float* fa0 = (const float*)&bufA[0][0];
            const float* fa1 = (const float*)&bufA[1][0];
            const float* fbb = (const float*)&bufB[0];
#pragma unroll
            for (int q2 = 0; q2 < 8; ++q2) {
                sqA0 = fmaf(fa0[q2], fa0[q2], sqA0);
                sqA1 = fmaf(fa1[q2], fa1[q2], sqA1);
                sqB  = fmaf(fbb[q2], fbb[q2], sqB);
            }
            uint4 v;
            v.x = pk_bf2(fa0[0], fa0[1]); v.y = pk_bf2(fa0[2], fa0[3]);
            v.z = pk_bf2(fa0[4], fa0[5]); v.w = pk_bf2(fa0[6], fa0[7]);
            *(uint4*)(nst + swz(aRow0, aKg0 * 8)) = v;
            v.x = pk_bf2(fa1[0], fa1[1]); v.y = pk_bf2(fa1[2], fa1[3]);
            v.z = pk_bf2(fa1[4], fa1[5]); v.w = pk_bf2(fa1[6], fa1[7]);
            *(uint4*)(nst + swz(aRow1, aKg1 * 8)) = v;
            v.x = pk_bf2(fbb[0], fbb[1]); v.y = pk_bf2(fbb[2], fbb[3]);
            v.z = pk_bf2(fbb[4], fbb[5]); v.w = pk_bf2(fbb[6], fbb[7]);
            *(uint4*)(nst + 8192 + swz(bRow, bKg * 8)) = v;
        }
        __syncthreads();
    }

    sqA0 += __shfl_xor_sync(0xffffffffu, sqA0, 1);
    sqA0 += __shfl_xor_sync(0xffffffffu, sqA0, 2);
    sqA1 += __shfl_xor_sync(0xffffffffu, sqA1, 1);
    sqA1 += __shfl_xor_sync(0xffffffffu, sqA1, 2);
    sqB  += __shfl_xor_sync(0xffffffffu, sqB, 1);
    sqB  += __shfl_xor_sync(0xffffffffu, sqB, 2);

    if (mode == 1) {
        if ((tid & 3) == 0) {
            g_nAL[kh][p_idx][aRow0] = sqA0;
            g_nAL[kh][p_idx][aRow1] = sqA1;
            g_nBL[kh][p_idx][colTile + bRow] = sqB;
        }
        int g8 = lane >> 2, tq = lane & 3;
#pragma unroll
        for (int tm = 0; tm < 2; ++tm) {
            int row0 = wm * 32 + tm * 16 + g8;
            int row1 = row0 + 8;
#pragma unroll
            for (int tn = 0; tn < 4; ++tn) {
                int col = colTile + wn * 32 + tn * 8 + 2 * tq;
                *(float2*)(out + row0 * Ll + col) =
                    make_float2(acc[tm][tn][0], acc[tm][tn][1]);
                *(float2*)(out + row1 * Ll + col) =
                    make_float2(acc[tm][tn][2], acc[tm][tn][3]);
            }
        }
        return;
    }

    if ((tid & 3) == 0) {
        rnAs[aRow0] = rsqrtf(sqA0);
        rnAs[aRow1] = rsqrtf(sqA1);
        rnBs[bRow]  = rsqrtf(sqB);
    }
    __syncthreads();

    int g8 = lane >> 2, tq = lane & 3;
#pragma unroll
    for (int tm = 0; tm < 2; ++tm) {
        int row0 = wm * 32 + tm * 16 + g8;
        int row1 = row0 + 8;
        float ra0 = rnAs[row0], ra1 = rnAs[row1];
#pragma unroll
        for (int tn = 0; tn < 4; ++tn) {
            int lcol = wn * 32 + tn * 8 + 2 * tq;
            int col = colTile + lcol;
            float rb0 = rnBs[lcol], rb1 = rnBs[lcol + 1];
            float v00 = acc[tm][tn][0] * ra0 * rb0 * FSD_SCALE;
            float v01 = acc[tm][tn][1] * ra0 * rb1 * FSD_SCALE;
            float v10 = acc[tm][tn][2] * ra1 * rb0 * FSD_SCALE;
            float v11 = acc[tm][tn][3] * ra1 * rb1 * FSD_SCALE;
            *(float2*)(out + row0 * Ll + col) = make_float2(v00, v01);
            *(float2*)(out + row1 * Ll + col) = make_float2(v10, v11);
        }
    }
}

// ---------------------------------------------------------------------------
// k_dp: 64 blocks x 128 threads. 4 warps, 1 row/lane, lagged-epoch schedule.
// DPK=8; each superstep PREFETCHES its 8 (m,g) and 8 bnd values into
// registers first (off the recurrence chain), then runs 8 branchless cells.
// ---------------------------------------------------------------------------
__device__ __forceinline__ float ex2f(float x) {
    float y; asm("ex2.approx.f32 %0, %1;" : "=f"(y) : "f"(x)); return y;
}
__device__ __forceinline__ float lg2f(float x) {
    float y; asm("lg2.approx.f32 %0, %1;" : "=f"(y) : "f"(x)); return y;
}

#define DPK 8       // diagonals per epoch
#define NSUP 35     // supersteps: epochs 32, warp w active tau in [4w, 4w+32)... window below

__global__ void k_dp(float* __restrict__ outp) {
    extern __shared__ float dsm[];
    __shared__ float bnd[5][256];       // rows 0..3 per-warp boundaries, row 4 zeros
    int b = blockIdx.x;
    int tid = threadIdx.x;
    bool isFsd = (b < 32);
    int pair = isFsd ? b : b - 32;

    if (isFsd) {
        // pack (m, g) as float2; float2 linear index == row-major element index
        float4* o4 = (float4*)dsm;
        const float4* Mb = (const float4*)(g_sim_m + (size_t)pair * 16384);
        const float4* Gb = (const float4*)(g_sim_g + (size_t)pair * 16384);
        for (int i = tid; i < 4096; i += 128) {
            float4 m4 = Mb[i];
            float4 g4 = Gb[i];
            o4[2 * i + 0] = make_float4(m4.x, g4.x, m4.y, g4.y);
            o4[2 * i + 1] = make_float4(m4.z, g4.z, m4.w, g4.w);
        }
    } else {
        // fused LCS split-K epilogue into plain float smem
        __shared__ float rA[128], rB[128];
        rA[tid] = rsqrtf(g_nAL[0][pair][tid] + g_nAL[1][pair][tid]);
        rB[tid] = rsqrtf(g_nBL[0][pair][tid] + g_nBL[1][pair][tid]);
        __syncthreads();
        const float* d0 = g_dotL0 + (size_t)pair * 16384;
        const float* d1 = g_dotL1 + (size_t)pair * 16384;
        for (int idx = tid * 4; idx < 16384; idx += 512) {
            float4 a4 = *(const float4*)(d0 + idx);
            float4 b4 = *(const float4*)(d1 + idx);
            int row = idx >> 7, col = idx & 127;
            float ra = rA[row];
            float4 r;
            r.x = fmaxf(0.0f, (a4.x + b4.x) * ra * rB[col + 0] - 0.8f) * 5.0f;
            r.y = fmaxf(0.0f, (a4.y + b4.y) * ra * rB[col + 1] - 0.8f) * 5.0f;
            r.z = fmaxf(0.0f, (a4.z + b4.z) * ra * rB[col + 2] - 0.8f) * 5.0f;
            r.w = fmaxf(0.0f, (a4.w + b4.w) * ra * rB[col + 3] - 0.8f) * 5.0f;
            *(float4*)(dsm + idx) = r;
        }
    }
    // zero boundary row
    bnd[4][tid] = 0.0f;
    bnd[4][tid + 128] = 0.0f;
    __syncthreads();

    int w = tid >> 5, lane = tid & 31;
    int r = tid;                        // row owned by this thread
    const float* bndp = bnd[(w == 0) ? 4 : (w - 1)];
    float v = 0.0f, d = 0.0f;

    // warp w active during supersteps tau in [w, w + 32): epoch e = tau - w,
    // diagonals [e*8, e*8+8). 32 epochs cover s in [0,256).
    if (isFsd) {
        const float2* mrow = ((const float2*)dsm) + r * 127;
        for (int tau = 0; tau < NSUP; ++tau) {
            if (tau >= w && tau < w + 32) {
                int s0 = (tau - w) * DPK;
                float2 mgb[DPK];
                float  bvb[DPK];
#pragma unroll
                for (int k = 0; k < DPK; ++k) {
                    int s = s0 + k;
                    int sl = (s < 255) ? s : 254;
                    int sm1 = s - 1; if (sm1 < 0) sm1 = 0;
                    mgb[k] = mrow[sl];
                    bvb[k] = bndp[sm1];
                }
#pragma unroll
                for (int k = 0; k < DPK; ++k) {
                    int s = s0 + k;
                    float au = __shfl_up_sync(0xffffffffu, v, 1);
                    float a = (lane == 0) ? bvb[k] : au;
                    float x1 = mgb[k].y + a, x2 = mgb[k].y + v;
                    float mx = fmaxf(fmaxf(d, x1), x2);
                    float e = ex2f(d - mx) + ex2f(x1 - mx) + ex2f(x2 - mx);
                    float nv = mgb[k].x + mx + lg2f(e);
                    v = ((unsigned)(s - r) < 128u) ? nv : v;
                    d = a;
                    if (lane == 31) bnd[w][s] = v;
                }
            }
            __syncthreads();
        }
        if (tid == 127) g_dpres[b] = v * FSD_UNSCALE;
    } else {
        const float* mrow = dsm + r * 127;
        for (int tau = 0; tau < NSUP; ++tau) {
            if (tau >= w && tau < w + 32) {
                int s0 = (tau - w) * DPK;
                float mb[DPK];
                float bvb[DPK];
#pragma unroll
                for (int k = 0; k < DPK; ++k) {
                    int s = s0 + k;
                    int sl = (s < 255) ? s : 254;
                    int sm1 = s - 1; if (sm1 < 0) sm1 = 0;
                    mb[k] = mrow[sl];
                    bvb[k] = bndp[sm1];
                }
#pragma unroll
                for (int k = 0; k < DPK; ++k) {
                    int s = s0 + k;
                    float au = __shfl_up_sync(0xffffffffu, v, 1);
                    float a = (lane == 0) ? bvb[k] : au;
                    float nv = (mb[k] > 0.5f) ? d + mb[k] : fmaxf(a, v);
                    v = ((unsigned)(s - r) < 128u) ? nv : v;
                    d = a;
                    if (lane == 31) bnd[w][s] = v;
                }
            }
            __syncthreads();
        }
        if (tid == 127) g_dpres[b] = v;
    }

    // completion + final combine by the last finishing block
    if (tid == 127) {
        __threadfence();
        unsigned vdone = atomicAdd(&g_done, 1u);
        if (vdone == 63u) {
            float cls = 0.f, guide = 0.f, feat = 0.f, sparse = 0.f;
#pragma unroll 4
            for (int i = 0; i < 32; ++i) {
                cls    += g_small[i][0];
                guide  += g_small[i][1];
                feat   += g_small[i][2];
                sparse += g_small[i][3];
            }
            volatile float* dp = g_dpres;
            float aa = 0.f, ab = 0.f, pl = 0.f, nl = 0.f;
#pragma unroll 4
            for (int i = 0; i < 16; ++i) {
                aa += dp[i];
                ab += dp[16 + i];
                pl += dp[32 + i];
                nl += dp[48 + i];
            }
            float acm = cls / 32.0f + guide / 32.0f
                      + 5e-5f * (feat / 32.0f) + 2e-4f * (sparse / 64.0f);
            outp[0] = acm + 0.1f * ((nl - pl) / 16.0f)
                          + 0.1f * ((ab - aa) / 16.0f);
            g_done = 0;
        }
    }
}

// ---------------------------------------------------------------------------
// Launch
// ---------------------------------------------------------------------------
extern "C" void kernel_launch(void* const* d_in, const int* in_sizes, int n_in,
                              void* d_out, int out_size) {
    const float* xi  = (const float*)d_in[0];
    const float* xc  = (const float*)d_in[1];
    const float* xb  = (const float*)d_in[2];
    const float* vid = (const float*)d_in[3];
    const float* att = (const float*)d_in[4];
    const float* fi  = (const float*)d_in[5];
    const float* fc  = (const float*)d_in[6];
    const float* fb  = (const float*)d_in[7];
    const float* cas = (const float*)d_in[8];
    const float* lcs = (const float*)d_in[9];
    const float* act = (const float*)d_in[10];
    const float* bak = (const float*)d_in[11];
    const int*   pos = (const int*)d_in[12];
    const int*   neg = (const int*)d_in[13];
    float* out = (float*)d_out;

    const int dp_smem = 2 * 16384 * (int)sizeof(float);   // 128 KB
    cudaFuncSetAttribute(k_dp, cudaFuncAttributeMaxDynamicSharedMemorySize, dp_smem);

    k_gemm<<<288, 256>>>(lcs, act, bak, pos, neg,
                         xi, xc, xb, vid, att, fi, fc, fb, cas);
    k_dp<<<64, 128, dp_smem>>>(out);
}

// round 16
// speedup vs baseline: 1.4615x; 1.0027x over previous
#include <cuda_runtime.h>
#include <cuda_bf16.h>
#include <stdint.h>
#include <math.h>

#define Bv    32
#define NCLS  20
#define Tt    2048
#define Dd    2048
#define Ll    128

// FSD scale: 10*log2(e)  (gamma=0.1 -> log2 x10 domain); back: ln(2)/10
#define FSD_SCALE 14.426950408889634f
#define FSD_UNSCALE 0.06931471805599453f

// ---------------------------------------------------------------------------
// Device scratch
// ---------------------------------------------------------------------------
__device__ float g_sim_m[32 * Ll * Ll];     // FSD m (x FSD_SCALE)
__device__ float g_sim_g[32 * Ll * Ll];     // FSD g (x FSD_SCALE)
__device__ float g_dotL0[32 * Ll * Ll];     // LCS raw dots, K half 0
__device__ float g_dotL1[32 * Ll * Ll];     // LCS raw dots, K half 1
__device__ float g_nAL[2][32][128];         // LCS A sq partials
__device__ float g_nBL[2][32][128];         // LCS B sq partials
__device__ float g_small[32][4];            // per-batch {cls, guide, feat, sparse}
__device__ float g_dpres[64];               // 0..31 fsd, 32..63 lcs
__device__ unsigned int g_done = 0;

// ---------------------------------------------------------------------------
// GEMM helpers
// ---------------------------------------------------------------------------
__device__ __forceinline__ uint32_t swz(uint32_t row, uint32_t col) {
    return row * 64u + ((((col >> 3) ^ ((row >> 1) & 3u)) << 4)) + ((col & 7u) << 1);
}
__device__ __forceinline__ uint32_t pk_bf2(float lo, float hi) {
    __nv_bfloat162 h = __floats2bfloat162_rn(lo, hi);
    return *(uint32_t*)&h;
}
__device__ __forceinline__ void ldsm4(uint32_t addr, uint32_t& r0, uint32_t& r1,
                                      uint32_t& r2, uint32_t& r3) {
    asm volatile("ldmatrix.sync.aligned.m8n8.x4.shared.b16 {%0,%1,%2,%3}, [%4];"
                 : "=r"(r0), "=r"(r1), "=r"(r2), "=r"(r3) : "r"(addr));
}
__device__ __forceinline__ void mma16816(float* c, const uint32_t* a,
                                         uint32_t b0, uint32_t b1) {
    asm volatile("mma.sync.aligned.m16n8k16.row.col.f32.bf16.bf16.f32 "
                 "{%0,%1,%2,%3}, {%4,%5,%6,%7}, {%8,%9}, {%0,%1,%2,%3};"
                 : "+f"(c[0]), "+f"(c[1]), "+f"(c[2]), "+f"(c[3])
                 : "r"(a[0]), "r"(a[1]), "r"(a[2]), "r"(a[3]), "r"(b0), "r"(b1));
}

#define STAGE_BYTES 12288
#define KSTEPS 32

// ---------------------------------------------------------------------------
// k_gemm: 288 blocks.
//  [0,128) FSD final. [128,256) LCS split-K raw. [256,288) small-loss blocks.
// ---------------------------------------------------------------------------
__global__ __launch_bounds__(256, 2)
void k_gemm(const float* __restrict__ lcs,
            const float* __restrict__ act,
            const float* __restrict__ bak,
            const int* __restrict__ pos,
            const int* __restrict__ neg,
            const float* __restrict__ xi,
            const float* __restrict__ xc,
            const float* __restrict__ xb,
            const float* __restrict__ vid,
            const float* __restrict__ att,
            const float* __restrict__ fi,
            const float* __restrict__ fc,
            const float* __restrict__ fb,
            const float* __restrict__ cas) {
    int blk = blockIdx.x;
    int tid = threadIdx.x;

    __shared__ uint4 smBuf[2 * STAGE_BYTES / 16];
    __shared__ float rnAs[128];
    __shared__ float rnBs[64];

    if (blk >= 256) {
        __shared__ float red[256];
        int bb = blk - 256;
        float guide = 0.0f, sparse = 0.0f, si2 = 0.0f, sc2 = 0.0f, sb2 = 0.0f;
        for (int tt = tid; tt < Tt; tt += 256) {
            float cas20 = cas[((size_t)bb * Tt + tt) * (NCLS + 1) + NCLS];
            float a0 = att[((size_t)bb * Tt + tt) * 3 + 0];
            float a1 = att[((size_t)bb * Tt + tt) * 3 + 1];
            guide  += fabsf(1.0f - cas20 - a0);
            sparse += a0 + a1;
        }
        for (int k = tid; k < Dd; k += 256) {
            float v1 = fi[(size_t)bb * Dd + k];
            float v2 = fc[(size_t)bb * Dd + k];
            float v3 = fb[(size_t)bb * Dd + k];
            si2 += v1 * v1; sc2 += v2 * v2; sb2 += v3 * v3;
        }
        float vals[5] = {guide, sparse, si2, sc2, sb2};
#pragma unroll
        for (int v = 0; v < 5; ++v) {
            red[tid] = vals[v];
            __syncthreads();
            for (int s = 128; s > 0; s >>= 1) {
                if (tid < s) red[tid] += red[tid + s];
                __syncthreads();
            }
            vals[v] = red[0];
            __syncthreads();
        }
        if (tid == 0) {
            float ni = sqrtf(vals[2]);
            float nc = sqrtf(vals[3]);
            float nb = sqrtf(vals[4]);
            float f1 = fmaxf(50.0f - ni + nc, 0.0f);
            float f2 = fmaxf(50.0f - nc + nb, 0.0f);
            float feat = (f1 + f2 + nb) * (f1 + f2 + nb);
            float sv = 0.0f, s_i = 0.0f, s_c = 0.0f;
            for (int c = 0; c < NCLS; ++c) {
                float l = vid[bb * NCLS + c];
                sv  += l;
                s_i += l * logf(xi[bb * (NCLS + 1) + c] + 1e-45f);
                s_c += l * logf(xc[bb * (NCLS + 1) + c] + 1e-45f);
            }
            float inst_b = -s_i / sv;
            float cont_b = -(s_c + logf(xc[bb * (NCLS + 1) + NCLS] + 1e-45f)) / (sv + 1.0f);
            float back_b = -logf(xb[bb * (NCLS + 1) + NCLS] + 1e-45f);
            g_small[bb][0] = inst_b + cont_b + back_b;
            g_small[bb][1] = vals[0];
            g_small[bb][2] = feat;
            g_small[bb][3] = vals[1];
        }
        return;
    }

    const float *Abase, *Bbase;
    float* out;
    int mode, colTile, p_idx, kh = 0;

    if (blk < 128) {
        int f = blk >> 1;
        colTile = (blk & 1) * 64;
        int p = f >> 1;
        int half = f & 1;
        p_idx = p;
        int i0 = (p < 16) ? pos[2 * p]     : neg[2 * (p - 16)];
        int i1 = (p < 16) ? pos[2 * p + 1] : neg[2 * (p - 16) + 1];
        Abase = act + (size_t)i0 * Ll * Dd + half * 1024;
        if (p < 16)
            Bbase = act + (size_t)i1 * Ll * Dd + half * 1024;
        else
            Bbase = bak + (size_t)i1 * Ll * Dd + half * 1024;
        out = (half ? g_sim_g : g_sim_m) + (size_t)p * Ll * Ll;
        mode = 0;
    } else {
        int q = blk - 128;
        int p = q >> 2;
        colTile = ((q >> 1) & 1) * 64;
        kh = q & 1;
        p_idx = p;
        int i0 = (p < 16) ? pos[2 * p]     : neg[2 * (p - 16)];
        int i1 = (p < 16) ? pos[2 * p + 1] : neg[2 * (p - 16) + 1];
        Abase = lcs + (size_t)i0 * Ll * Dd + kh * 1024;
        Bbase = lcs + (size_t)i1 * Ll * Dd + kh * 1024;
        out = (kh ? g_dotL1 : g_dotL0) + (size_t)p * Ll * Ll;
        mode = 1;
    }
    Bbase += (size_t)colTile * Dd;

    char* smc = (char*)smBuf;
    uint32_t smemBase = (uint32_t)__cvta_generic_to_shared(smc);

    int lane = tid & 31;
    int warp = tid >> 5;
    int wm = warp >> 1;
    int wn = warp & 1;

    int aRow0 = tid >> 2,            aKg0 = tid & 3;
    int aRow1 = (tid + 256) >> 2,    aKg1 = tid & 3;
    int bRow  = tid >> 2,            bKg  = tid & 3;

    float acc[2][4][4];
#pragma unroll
    for (int i = 0; i < 2; ++i)
#pragma unroll
        for (int j = 0; j < 4; ++j)
#pragma unroll
            for (int q2 = 0; q2 < 4; ++q2) acc[i][j][q2] = 0.0f;

    float sqA0 = 0.0f, sqA1 = 0.0f, sqB = 0.0f;
    float4 bufA[2][2], bufB[2];

    const float* pA0 = Abase + (size_t)aRow0 * Dd + aKg0 * 8;
    const float* pA1 = Abase + (size_t)aRow1 * Dd + aKg1 * 8;
    const float* pB  = Bbase + (size_t)bRow  * Dd + bKg  * 8;

    bufA[0][0] = *(const float4*)(pA0);
    bufA[0][1] = *(const float4*)(pA0 + 4);
    bufA[1][0] = *(const float4*)(pA1);
    bufA[1][1] = *(const float4*)(pA1 + 4);
    bufB[0]    = *(const float4*)(pB);
    bufB[1]    = *(const float4*)(pB + 4);

    {
        const float* fa0 = (const float*)&bufA[0][0];
        const float* fa1 = (const float*)&bufA[1][0];
        const float* fbb = (const float*)&bufB[0];
#pragma unroll
        for (int q2 = 0; q2 < 8; ++q2) {
            sqA0 = fmaf(fa0[q2], fa0[q2], sqA0);
            sqA1 = fmaf(fa1[q2], fa1[q2], sqA1);
            sqB  = fmaf(fbb[q2], fbb[q2], sqB);
        }
        uint4 v;
        v.x = pk_bf2(fa0[0], fa0[1]); v.y = pk_bf2(fa0[2], fa0[3]);
        v.z = pk_bf2(fa0[4], fa0[5]); v.w = pk_bf2(fa0[6], fa0[7]);
        *(uint4*)(smc + swz(aRow0, aKg0 * 8)) = v;
        v.x = pk_bf2(fa1[0], fa1[1]); v.y = pk_bf2(fa1[2], fa1[3]);
        v.z = pk_bf2(fa1[4], fa1[5]); v.w = pk_bf2(fa1[6], fa1[7]);
        *(uint4*)(smc + swz(aRow1, aKg1 * 8)) = v;
        v.x = pk_bf2(fbb[0], fbb[1]); v.y = pk_bf2(fbb[2], fbb[3]);
        v.z = pk_bf2(fbb[4], fbb[5]); v.w = pk_bf2(fbb[6], fbb[7]);
        *(uint4*)(smc + 8192 + swz(bRow, bKg * 8)) = v;
    }
    __syncthreads();

    int grp = lane >> 3, r8 = lane & 7;
    uint32_t aRowL = (uint32_t)(r8 + (grp & 1) * 8);
    uint32_t aColL = (uint32_t)((grp >> 1) * 8);
    uint32_t bRowL = (uint32_t)(r8 + (grp >> 1) * 8);
    uint32_t bColL = (uint32_t)((grp & 1) * 8);

    for (int kt = 0; kt < KSTEPS; ++kt) {
        if (kt + 1 < KSTEPS) {
            int k0 = (kt + 1) * 32;
            bufA[0][0] = *(const float4*)(pA0 + k0);
            bufA[0][1] = *(const float4*)(pA0 + k0 + 4);
            bufA[1][0] = *(const float4*)(pA1 + k0);
            bufA[1][1] = *(const float4*)(pA1 + k0 + 4);
            bufB[0]    = *(const float4*)(pB + k0);
            bufB[1]    = *(const float4*)(pB + k0 + 4);
        }

        uint32_t stBase = smemBase + (uint32_t)(kt & 1) * STAGE_BYTES;
#pragma unroll
        for (int ks = 0; ks < 2; ++ks) {
            int k0 = ks * 16;
            uint32_t afr[2][4];
#pragma unroll
            for (int tm = 0; tm < 2; ++tm) {
                uint32_t m0 = (uint32_t)(wm * 32 + tm * 16);
                uint32_t addrA = stBase + swz(m0 + aRowL, (uint32_t)k0 + aColL);
                ldsm4(addrA, afr[tm][0], afr[tm][1], afr[tm][2], afr[tm][3]);
            }
            uint32_t bfr[2][4];
#pragma unroll
            for (int tb = 0; tb < 2; ++tb) {
                uint32_t n0 = (uint32_t)(wn * 32 + tb * 16);
                uint32_t addrB = stBase + 8192u + swz(n0 + bRowL, (uint32_t)k0 + bColL);
                ldsm4(addrB, bfr[tb][0], bfr[tb][1], bfr[tb][2], bfr[tb][3]);
            }
#pragma unroll
            for (int tm = 0; tm < 2; ++tm)
#pragma unroll
                for (int tn = 0; tn < 4; ++tn) {
                    int tb = tn >> 1, wh = tn & 1;
                    mma16816(acc[tm][tn], afr[tm], bfr[tb][wh * 2], bfr[tb][wh * 2 + 1]);
                }
        }

        if (kt + 1 < KSTEPS) {
            char* nst = smc + ((kt + 1) & 1) * STAGE_BYTES;
            const float* fa0 = (const float*)&bufA[0][0];
            const float* fa1 = (const float*)&bufA[1][0];
            const float* fbb = (const float*)&bufB[0];
#pragma unroll
            for (int q2 = 0; q2 < 8; ++q2) {
                sqA0 = fmaf(fa0[q2], fa0[q2], sqA0);
                sqA1 = fmaf(fa1[q2], fa1[q2], sqA1);
                sqB  = fmaf(fbb[q2], fbb[q2], sqB);
            }
            uint4 v;
            v.x = pk_bf2(fa0[0], fa0[1]); v.y = pk_bf2(fa0[2], fa0[3]);
            v.z = pk_bf2(fa0[4], fa0[5]); v.w = pk_bf2(fa0[6], fa0[7]);
            *(uint4*)(nst + swz(aRow0, aKg0 * 8)) = v;
            v.x = pk_bf2(fa1[0], fa1[1]); v.y = pk_bf2(fa1[2], fa1[3]);
            v.z = pk_bf2(fa1[4], fa1[5]); v.w = pk_bf2(fa1[6], fa1[7]);
            *(uint4*)(nst + swz(aRow1, aKg1 * 8)) = v;
            v.x = pk_bf2(fbb[0], fbb[1]); v.y = pk_bf2(fbb[2], fbb[3]);
            v.z = pk_bf2(fbb[4], fbb[5]); v.w = pk_bf2(fbb[6], fbb[7]);
            *(uint4*)(nst + 8192 + swz(bRow, bKg * 8)) = v;
        }
        __syncthreads();
    }

    sqA0 += __shfl_xor_sync(0xffffffffu, sqA0, 1);
    sqA0 += __shfl_xor_sync(0xffffffffu, sqA0, 2);
    sqA1 += __shfl_xor_sync(0xffffffffu, sqA1, 1);
    sqA1 += __shfl_xor_sync(0xffffffffu, sqA1, 2);
    sqB  += __shfl_xor_sync(0xffffffffu, sqB, 1);
    sqB  += __shfl_xor_sync(0xffffffffu, sqB, 2);

    if (mode == 1) {
        if ((tid & 3) == 0) {
            g_nAL[kh][p_idx][aRow0] = sqA0;
            g_nAL[kh][p_idx][aRow1] = sqA1;
            g_nBL[kh][p_idx][colTile + bRow] = sqB;
        }
        int g8 = lane >> 2, tq = lane & 3;
#pragma unroll
        for (int tm = 0; tm < 2; ++tm) {
            int row0 = wm * 32 + tm * 16 + g8;
            int row1 = row0 + 8;
#pragma unroll
            for (int tn = 0; tn < 4; ++tn) {
                int col = colTile + wn * 32 + tn * 8 + 2 * tq;
                *(float2*)(out + row0 * Ll + col) =
                    make_float2(acc[tm][tn][0], acc[tm][tn][1]);
                *(float2*)(out + row1 * Ll + col) =
                    make_float2(acc[tm][tn][2], acc[tm][tn][3]);
            }
        }
        return;
    }

    if ((tid & 3) == 0) {
        rnAs[aRow0] = rsqrtf(sqA0);
        rnAs[aRow1] = rsqrtf(sqA1);
        rnBs[bRow]  = rsqrtf(sqB);
    }
    __syncthreads();

    int g8 = lane >> 2, tq = lane & 3;
#pragma unroll
    for (int tm = 0; tm < 2; ++tm) {
        int row0 = wm * 32 + tm * 16 + g8;
        int row1 = row0 + 8;
        float ra0 = rnAs[row0], ra1 = rnAs[row1];
#pragma unroll
        for (int tn = 0; tn < 4; ++tn) {
            int lcol = wn * 32 + tn * 8 + 2 * tq;
            int col = colTile + lcol;
            float rb0 = rnBs[lcol], rb1 = rnBs[lcol + 1];
            float v00 = acc[tm][tn][0] * ra0 * rb0 * FSD_SCALE;
            float v01 = acc[tm][tn][1] * ra0 * rb1 * FSD_SCALE;
            float v10 = acc[tm][tn][2] * ra1 * rb0 * FSD_SCALE;
            float v11 = acc[tm][tn][3] * ra1 * rb1 * FSD_SCALE;
            *(float2*)(out + row0 * Ll + col) = make_float2(v00, v01);
            *(float2*)(out + row1 * Ll + col) = make_float2(v10, v11);
        }
    }
}

// ---------------------------------------------------------------------------
// k_dp: 64 blocks x 128 threads. 4 warps, 1 row/lane, lagged-epoch schedule.
// DPK=8; each superstep PREFETCHES its 8 (m,g) and 8 bnd values into
// registers first (off the recurrence chain), then runs 8 branchless cells.
// ---------------------------------------------------------------------------
__device__ __forceinline__ float ex2f(float x) {
    float y; asm("ex2.approx.f32 %0, %1;" : "=f"(y) : "f"(x)); return y;
}
__device__ __forceinline__ float lg2f(float x) {
    float y; asm("lg2.approx.f32 %0, %1;" : "=f"(y) : "f"(x)); return y;
}

#define DPK 8       // diagonals per epoch
#define NSUP 35     // supersteps: epochs 32, warp w active tau in [4w, 4w+32)... window below

__global__ void k_dp(float* __restrict__ outp) {
    extern __shared__ float dsm[];
    __shared__ float bnd[5][256];       // rows 0..3 per-warp boundaries, row 4 zeros
    int b = blockIdx.x;
    int tid = threadIdx.x;
    bool isFsd = (b < 32);
    int pair = isFsd ? b : b - 32;

    if (isFsd) {
        // pack (m, g) as float2; float2 linear index == row-major element index
        float4* o4 = (float4*)dsm;
        const float4* Mb = (const float4*)(g_sim_m + (size_t)pair * 16384);
        const float4* Gb = (const float4*)(g_sim_g + (size_t)pair * 16384);
        for (int i = tid; i < 4096; i += 128) {
            float4 m4 = Mb[i];
            float4 g4 = Gb[i];
            o4[2 * i + 0] = make_float4(m4.x, g4.x, m4.y, g4.y);
            o4[2 * i + 1] = make_float4(m4.z, g4.z, m4.w, g4.w);
        }
    } else {
        // fused LCS split-K epilogue into plain float smem
        __shared__ float rA[128], rB[128];
        rA[tid] = rsqrtf(g_nAL[0][pair][tid] + g_nAL[1][pair][tid]);
        rB[tid] = rsqrtf(g_nBL[0][pair][tid] + g_nBL[1][pair][tid]);
        __syncthreads();
        const float* d0 = g_dotL0 + (size_t)pair * 16384;
        const float* d1 = g_dotL1 + (size_t)pair * 16384;
        for (int idx = tid * 4; idx < 16384; idx += 512) {
            float4 a4 = *(const float4*)(d0 + idx);
            float4 b4 = *(const float4*)(d1 + idx);
            int row = idx >> 7, col = idx & 127;
            float ra = rA[row];
            float4 r;
            r.x = fmaxf(0.0f, (a4.x + b4.x) * ra * rB[col + 0] - 0.8f) * 5.0f;
            r.y = fmaxf(0.0f, (a4.y + b4.y) * ra * rB[col + 1] - 0.8f) * 5.0f;
            r.z = fmaxf(0.0f, (a4.z + b4.z) * ra * rB[col + 2] - 0.8f) * 5.0f;
            r.w = fmaxf(0.0f, (a4.w + b4.w) * ra * rB[col + 3] - 0.8f) * 5.0f;
            *(float4*)(dsm + idx) = r;
        }
    }
    // zero boundary row
    bnd[4][tid] = 0.0f;
    bnd[4][tid + 128] = 0.0f;
    __syncthreads();

    int w = tid >> 5, lane = tid & 31;
    int r = tid;                        // row owned by this thread
    const float* bndp = bnd[(w == 0) ? 4 : (w - 1)];
    float v = 0.0f, d = 0.0f;

    // warp w active during supersteps tau in [w, w + 32): epoch e = tau - w,
    // diagonals [e*8, e*8+8). 32 epochs cover s in [0,256).
    if (isFsd) {
        const float2* mrow = ((const float2*)dsm) + r * 127;
        for (int tau = 0; tau < NSUP; ++tau) {
            if (tau >= w && tau < w + 32) {
                int s0 = (tau - w) * DPK;
                float2 mgb[DPK];
                float  bvb[DPK];
#pragma unroll
                for (int k = 0; k < DPK; ++k) {
                    int s = s0 + k;
                    int sl = (s < 255) ? s : 254;
                    int sm1 = s - 1; if (sm1 < 0) sm1 = 0;
                    mgb[k] = mrow[sl];
                    bvb[k] = bndp[sm1];
                }
#pragma unroll
                for (int k = 0; k < DPK; ++k) {
                    int s = s0 + k;
                    float au = __shfl_up_sync(0xffffffffu, v, 1);
                    float a = (lane == 0) ? bvb[k] : au;
                    float x1 = mgb[k].y + a, x2 = mgb[k].y + v;
                    float mx = fmaxf(fmaxf(d, x1), x2);
                    float e = ex2f(d - mx) + ex2f(x1 - mx) + ex2f(x2 - mx);
                    float nv = mgb[k].x + mx + lg2f(e);
                    v = ((unsigned)(s - r) < 128u) ? nv : v;
                    d = a;
                    if (lane == 31) bnd[w][s] = v;
                }
            }
            __syncthreads();
        }
        if (tid == 127) g_dpres[b] = v * FSD_UNSCALE;
    } else {
        const float* mrow = dsm + r * 127;
        for (int tau = 0; tau < NSUP; ++tau) {
            if (tau >= w && tau < w + 32) {
                int s0 = (tau - w) * DPK;
                float mb[DPK];
                float bvb[DPK];
#pragma unroll
                for (int k = 0; k < DPK; ++k) {
                    int s = s0 + k;
                    int sl = (s < 255) ? s : 254;
                    int sm1 = s - 1; if (sm1 < 0) sm1 = 0;
                    mb[k] = mrow[sl];
                    bvb[k] = bndp[sm1];
                }
#pragma unroll
                for (int k = 0; k < DPK; ++k) {
                    int s = s0 + k;
                    float au = __shfl_up_sync(0xffffffffu, v, 1);
                    float a = (lane == 0) ? bvb[k] : au;
                    float nv = (mb[k] > 0.5f) ? d + mb[k] : fmaxf(a, v);
                    v = ((unsigned)(s - r) < 128u) ? nv : v;
                    d = a;
                    if (lane == 31) bnd[w][s] = v;
                }
            }
            __syncthreads();
        }
        if (tid == 127) g_dpres[b] = v;
    }

    // completion + final combine by the last finishing block
    if (tid == 127) {
        __threadfence();
        unsigned vdone = atomicAdd(&g_done, 1u);
        if (vdone == 63u) {
            float cls = 0.f, guide = 0.f, feat = 0.f, sparse = 0.f;
#pragma unroll 4
            for (int i = 0; i < 32; ++i) {
                cls    += g_small[i][0];
                guide  += g_small[i][1];
                feat   += g_small[i][2];
                sparse += g_small[i][3];
            }
            volatile float* dp = g_dpres;
            float aa = 0.f, ab = 0.f, pl = 0.f, nl = 0.f;
#pragma unroll 4
            for (int i = 0; i < 16; ++i) {
                aa += dp[i];
                ab += dp[16 + i];
                pl += dp[32 + i];
                nl += dp[48 + i];
            }
            float acm = cls / 32.0f + guide / 32.0f
                      + 5e-5f * (feat / 32.0f) + 2e-4f * (sparse / 64.0f);
            outp[0] = acm + 0.1f * ((nl - pl) / 16.0f)
                          + 0.1f * ((ab - aa) / 16.0f);
            g_done = 0;
        }
    }
}

// ---------------------------------------------------------------------------
// Launch
// ---------------------------------------------------------------------------
extern "C" void kernel_launch(void* const* d_in, const int* in_sizes, int n_in,
                              void* d_out, int out_size) {
    const float* xi  = (const float*)d_in[0];
    const float* xc  = (const float*)d_in[1];
    const float* xb  = (const float*)d_in[2];
    const float* vid = (const float*)d_in[3];
    const float* att = (const float*)d_in[4];
    const float* fi  = (const float*)d_in[5];
    const float* fc  = (const float*)d_in[6];
    const float* fb  = (const float*)d_in[7];
    const float* cas = (const float*)d_in[8];
    const float* lcs = (const float*)d_in[9];
    const float* act = (const float*)d_in[10];
    const float* bak = (const float*)d_in[11];
    const int*   pos = (const int*)d_in[12];
    const int*   neg = (const int*)d_in[13];
    float* out = (float*)d_out;

    const int dp_smem = 2 * 16384 * (int)sizeof(float);   // 128 KB
    cudaFuncSetAttribute(k_dp, cudaFuncAttributeMaxDynamicSharedMemorySize, dp_smem);

    k_gemm<<<288, 256>>>(lcs, act, bak, pos, neg,
                         xi, xc, xb, vid, att, fi, fc, fb, cas);
    k_dp<<<64, 128, dp_smem>>>(out);
}